// round 8
// baseline (speedup 1.0000x reference)
#include <cuda_runtime.h>
#include <cuda_fp16.h>
#include <cstdint>

// Problem constants (fixed by the reference)
#define M_ITEMS 100000
#define N_USERS 50000
#define DIM     64
#define NB      (M_ITEMS * DIM)   // 6,400,000 floats
#define NU      (N_USERS * DIM)   // 3,200,000 floats
#define E_II_MAX 3200000

#define SCAN_CHUNK  1024
#define SCAN_BLOCKS ((M_ITEMS + SCAN_CHUNK - 1) / SCAN_CHUNK)  // 98

// Static device scratch (no allocations allowed).
// Half layer buffers stored as uint4 (8 halves = one 16B gather unit per lane).
__device__ uint4 g_h0[NB / 8];          // half layer buffer (emb, then e2)
__device__ uint4 g_h1[NB / 8];          // half layer buffer (e1)
__device__ float g_sum[NB];             // running fp32 sum of layer embeddings
__device__ float g_users[NU];           // all_users (only batch rows are zeroed/used)
__device__ int   g_cnt[M_ITEMS];        // per-row counts (zeroed by k_scan_final each run)
__device__ int   g_rowptr[M_ITEMS + 1]; // CSR row pointers
__device__ int   g_pos[M_ITEMS];        // scatter fill cursors
__device__ int2  g_epack[E_II_MAX];     // CSR: packed (dst, val-bits) per edge
__device__ int   g_part[SCAN_BLOCKS];   // scan partials
__device__ unsigned char g_uflag[N_USERS]; // batch-user flags (set-only, idempotent)

// Vector reduction-add to global (sm_90+)
__device__ __forceinline__ void red_add_f4(float4* addr, float4 v) {
    asm volatile("red.global.add.v4.f32 [%0], {%1, %2, %3, %4};"
                 :: "l"(addr), "f"(v.x), "f"(v.y), "f"(v.z), "f"(v.w)
                 : "memory");
}

// Fused: g_sum = emb (fp32), g_h0 = half(emb) [vectorized], histogram of ii_src.
// g_cnt is zero on entry: static zero-init on first run, re-zeroed by k_scan_final.
__global__ void k_pre(const float* __restrict__ emb, const int* __restrict__ src, int ne) {
    int i = blockIdx.x * blockDim.x + threadIdx.x;
    if (i < NB / 8) {
        const float4* e4 = (const float4*)emb;
        float4 a = __ldg(e4 + 2 * i);
        float4 b = __ldg(e4 + 2 * i + 1);
        ((float4*)g_sum)[2 * i]     = a;
        ((float4*)g_sum)[2 * i + 1] = b;
        __half2 h0 = __floats2half2_rn(a.x, a.y);
        __half2 h1 = __floats2half2_rn(a.z, a.w);
        __half2 h2 = __floats2half2_rn(b.x, b.y);
        __half2 h3 = __floats2half2_rn(b.z, b.w);
        uint4 hp;
        hp.x = *reinterpret_cast<unsigned int*>(&h0);
        hp.y = *reinterpret_cast<unsigned int*>(&h1);
        hp.z = *reinterpret_cast<unsigned int*>(&h2);
        hp.w = *reinterpret_cast<unsigned int*>(&h3);
        g_h0[i] = hp;
    }
    if (i < ne) atomicAdd(&g_cnt[__ldg(src + i)], 1);
}

// Flag batch users + zero exactly their g_users rows (16 threads/user, 1 float4 each).
__global__ void k_flag_zero(const int* __restrict__ users, int nusers) {
    int t = blockIdx.x * blockDim.x + threadIdx.x;
    int b = t >> 4;
    int l = t & 15;
    if (b >= nusers) return;
    int u = __ldg(users + b);
    if (l == 0) g_uflag[u] = 1;
    ((float4*)g_users)[(long)u * 16 + l] = make_float4(0.f, 0.f, 0.f, 0.f);
}

// pass 1: per-1024-chunk sums
__global__ void k_scan_part() {
    __shared__ int s[256];
    int tid  = threadIdx.x;
    int base = blockIdx.x * SCAN_CHUNK;
    int sum = 0;
    #pragma unroll
    for (int i = 0; i < 4; i++) {
        int idx = base + tid + i * 256;
        if (idx < M_ITEMS) sum += g_cnt[idx];
    }
    s[tid] = sum;
    __syncthreads();
    for (int off = 128; off; off >>= 1) {
        if (tid < off) s[tid] += s[tid + off];
        __syncthreads();
    }
    if (tid == 0) g_part[blockIdx.x] = s[0];
}

// pass 2 (fused top+final): every block scans the 98 partials itself, then its
// local exclusive scan; writes rowptr/pos and zeroes g_cnt for the next replay.
__global__ void k_scan_final() {
    __shared__ int s[256];
    __shared__ int spart[128];
    int tid = threadIdx.x;

    if (tid < 128) spart[tid] = (tid < SCAN_BLOCKS) ? g_part[tid] : 0;
    __syncthreads();
    for (int off = 1; off < 128; off <<= 1) {
        int t = (tid < 128 && tid >= off) ? spart[tid - off] : 0;
        __syncthreads();
        if (tid < 128) spart[tid] += t;
        __syncthreads();
    }
    int blockOff = (blockIdx.x == 0) ? 0 : spart[blockIdx.x - 1];

    int idx0 = blockIdx.x * SCAN_CHUNK + tid * 4;
    int c[4];
    #pragma unroll
    for (int i = 0; i < 4; i++) {
        int idx = idx0 + i;
        c[i] = (idx < M_ITEMS) ? g_cnt[idx] : 0;
    }
    s[tid] = c[0] + c[1] + c[2] + c[3];
    __syncthreads();
    for (int off = 1; off < 256; off <<= 1) {
        int t = (tid >= off) ? s[tid - off] : 0;
        __syncthreads();
        s[tid] += t;
        __syncthreads();
    }
    int run = blockOff + ((tid == 0) ? 0 : s[tid - 1]);
    #pragma unroll
    for (int i = 0; i < 4; i++) {
        int idx = idx0 + i;
        if (idx < M_ITEMS) {
            g_rowptr[idx] = run;
            g_pos[idx]    = run;
            g_cnt[idx]    = 0;        // reset for next graph replay
            run += c[i];
        }
    }
    if (blockIdx.x == SCAN_BLOCKS - 1 && tid == 0)
        g_rowptr[M_ITEMS] = spart[SCAN_BLOCKS - 1];
}

// scatter edges into CSR order, 4 independent edges per thread (MLP=4 on the
// atomicAdd->store chains; previously MLP=1 made this latency-bound at 46us).
__global__ void k_scatter(const int* __restrict__ src, const int* __restrict__ dst,
                          const float* __restrict__ val, int n) {
    int i = blockIdx.x * blockDim.x + threadIdx.x;
    int Q = (n + 3) >> 2;
    if (i >= Q) return;
    int e[4]; int s[4]; int2 dv[4]; int p[4];
    #pragma unroll
    for (int k = 0; k < 4; k++) {
        e[k] = i + k * Q;
        if (e[k] < n) {
            s[k]  = __ldg(src + e[k]);
            dv[k] = make_int2(__ldg(dst + e[k]), __float_as_int(__ldg(val + e[k])));
        }
    }
    #pragma unroll
    for (int k = 0; k < 4; k++)
        if (e[k] < n) p[k] = atomicAdd(&g_pos[s[k]], 1);
    #pragma unroll
    for (int k = 0; k < 4; k++)
        if (e[k] < n) g_epack[p[k]] = dv[k];
}

// Pull SpMM, one warp per row, FOUR edges per iteration (8 lanes/edge).
// sub = lane>>3 picks the edge; lane8 = lane&7 covers 8 dims via one 16B load.
// fp32 accumulation; cross-subgroup combine via shfl_xor(8) + shfl_xor(16).
__global__ void k_spmm_pull(const uint4* __restrict__ x, uint4* __restrict__ yh,
                            const float* __restrict__ att, int layer) {
    int row  = blockIdx.x * (blockDim.x >> 5) + (threadIdx.x >> 5);
    int lane = threadIdx.x & 31;
    if (row >= M_ITEMS) return;
    int lane8 = lane & 7;
    int sub   = lane >> 3;

    int beg = g_rowptr[row];
    int end = g_rowptr[row + 1];

    float acc[8];
    #pragma unroll
    for (int k = 0; k < 8; k++) acc[k] = 0.0f;

    #pragma unroll 4
    for (int e = beg; e < end; e += 4) {
        int  idx = e + sub;
        bool ok  = idx < end;
        int2 ed  = __ldg(&g_epack[ok ? idx : beg]);
        float v  = ok ? __int_as_float(ed.y) : 0.0f;
        uint4 raw = __ldg(x + (long)ed.x * 8 + lane8);
        float2 f0 = __half22float2(*reinterpret_cast<__half2*>(&raw.x));
        float2 f1 = __half22float2(*reinterpret_cast<__half2*>(&raw.y));
        float2 f2 = __half22float2(*reinterpret_cast<__half2*>(&raw.z));
        float2 f3 = __half22float2(*reinterpret_cast<__half2*>(&raw.w));
        acc[0] = fmaf(v, f0.x, acc[0]);
        acc[1] = fmaf(v, f0.y, acc[1]);
        acc[2] = fmaf(v, f1.x, acc[2]);
        acc[3] = fmaf(v, f1.y, acc[3]);
        acc[4] = fmaf(v, f2.x, acc[4]);
        acc[5] = fmaf(v, f2.y, acc[5]);
        acc[6] = fmaf(v, f3.x, acc[6]);
        acc[7] = fmaf(v, f3.y, acc[7]);
    }
    #pragma unroll
    for (int k = 0; k < 8; k++) {
        acc[k] += __shfl_xor_sync(0xFFFFFFFFu, acc[k], 8);
        acc[k] += __shfl_xor_sync(0xFFFFFFFFu, acc[k], 16);
    }

    if (sub == 0) {
        float a = __ldg(att + layer);
        #pragma unroll
        for (int k = 0; k < 8; k++) acc[k] *= a;

        if (yh) {
            __half2 p0 = __floats2half2_rn(acc[0], acc[1]);
            __half2 p1 = __floats2half2_rn(acc[2], acc[3]);
            __half2 p2 = __floats2half2_rn(acc[4], acc[5]);
            __half2 p3 = __floats2half2_rn(acc[6], acc[7]);
            uint4 hp;
            hp.x = *reinterpret_cast<unsigned int*>(&p0);
            hp.y = *reinterpret_cast<unsigned int*>(&p1);
            hp.z = *reinterpret_cast<unsigned int*>(&p2);
            hp.w = *reinterpret_cast<unsigned int*>(&p3);
            yh[(long)row * 8 + lane8] = hp;
        }
        float4* sp = (float4*)g_sum + (long)row * 16 + lane8 * 2;
        float4 s0 = sp[0], s1 = sp[1];
        s0.x += acc[0]; s0.y += acc[1]; s0.z += acc[2]; s0.w += acc[3];
        s1.x += acc[4]; s1.y += acc[5]; s1.z += acc[6]; s1.w += acc[7];
        sp[0] = s0; sp[1] = s1;
    }
}

// user-item push SpMM, filtered to batch users (fp32 exact):
// g_users[src] += (val * 0.25) * g_sum[dst]
__global__ void k_spmm_ui(const int* __restrict__ src, const int* __restrict__ dst,
                          const float* __restrict__ val, int nedges) {
    long t = (long)blockIdx.x * blockDim.x + threadIdx.x;
    int e    = (int)(t >> 4);
    int lane = (int)(t & 15);
    if (e >= nedges) return;

    int s = __ldg(src + e);
    if (!g_uflag[s]) return;  // ~92% of edges exit here

    int   d = __ldg(dst + e);
    float v = __ldg(val + e) * 0.25f;

    float4 xv = __ldg((const float4*)g_sum + (long)d * 16 + lane);
    float4 r  = make_float4(xv.x * v, xv.y * v, xv.z * v, xv.w * v);
    red_add_f4((float4*)g_users + (long)s * 16 + lane, r);
}

// gamma[b] = dot(g_users[u], 0.25 * g_sum[i]); one warp per pair
__global__ void k_dot(const int* __restrict__ users, const int* __restrict__ items,
                      float* __restrict__ out, int nb) {
    int w    = (blockIdx.x * blockDim.x + threadIdx.x) >> 5;
    int lane = threadIdx.x & 31;
    if (w >= nb) return;

    int u = __ldg(users + w);
    int i = __ldg(items + w);

    float2 a = __ldg((const float2*)g_users + (long)u * 32 + lane);
    float2 b = __ldg((const float2*)g_sum   + (long)i * 32 + lane);
    float p = a.x * b.x + a.y * b.y;

    #pragma unroll
    for (int o = 16; o; o >>= 1) p += __shfl_xor_sync(0xFFFFFFFFu, p, o);

    if (lane == 0) out[w] = 0.25f * p;
}

extern "C" void kernel_launch(void* const* d_in, const int* in_sizes, int n_in,
                              void* d_out, int out_size) {
    const int*   users  = (const int*)d_in[0];
    const int*   items  = (const int*)d_in[1];
    const int*   ii_src = (const int*)d_in[2];
    const int*   ii_dst = (const int*)d_in[3];
    const float* ii_val = (const float*)d_in[4];
    const int*   ui_src = (const int*)d_in[5];
    const int*   ui_dst = (const int*)d_in[6];
    const float* ui_val = (const float*)d_in[7];
    const float* emb    = (const float*)d_in[8];
    const float* att    = (const float*)d_in[9];

    const int Eii = in_sizes[2];
    const int Eui = in_sizes[5];
    const int Bp  = in_sizes[0];

    const int TPB = 256;
    int preN = (NB / 8 > Eii) ? NB / 8 : Eii;
    const int preGrid  = (preN + TPB - 1) / TPB;
    const int scatGrid = (((Eii + 3) >> 2) + TPB - 1) / TPB;
    const int uiGrid   = (int)(((long)Eui * 16 + TPB - 1) / TPB);
    const int rowGrid  = (M_ITEMS + (TPB / 32) - 1) / (TPB / 32);

    uint4 *h0, *h1;
    cudaGetSymbolAddress((void**)&h0, g_h0);
    cudaGetSymbolAddress((void**)&h1, g_h1);

    // 0: fused init (sum/h0) + histogram;  1: flag + zero batch-user rows
    k_pre<<<preGrid, TPB>>>(emb, ii_src, Eii);
    k_flag_zero<<<(Bp * 16 + TPB - 1) / TPB, TPB>>>(users, Bp);
    // 2: scan part sums  (profile idx rotates; spmm L0 lands at idx 4... )
    k_scan_part <<<SCAN_BLOCKS, 256>>>();
    // 3: fused top+final scan (also re-zeroes g_cnt)
    k_scan_final<<<SCAN_BLOCKS, 256>>>();
    // 4: scatter into CSR, 4 edges/thread
    k_scatter<<<scatGrid, TPB>>>(ii_src, ii_dst, ii_val, Eii);

    // 5-7: pull-based LightGCN layers (sum fused, fp32 acc over half operands)
    k_spmm_pull<<<rowGrid, TPB>>>(h0, h1,      att, 0);  // emb -> e1
    k_spmm_pull<<<rowGrid, TPB>>>(h1, h0,      att, 1);  // e1  -> e2
    k_spmm_pull<<<rowGrid, TPB>>>(h0, nullptr, att, 2);  // e2  -> (sum only)

    // 8: user aggregation, filtered to batch users (0.25 mean folded in)
    k_spmm_ui<<<uiGrid, TPB>>>(ui_src, ui_dst, ui_val, Eui);

    // 9: final per-pair dots
    k_dot<<<(Bp * 32 + TPB - 1) / TPB, TPB>>>(users, items, (float*)d_out, Bp);
}

// round 9
// speedup vs baseline: 1.0241x; 1.0241x over previous
#include <cuda_runtime.h>
#include <cuda_fp16.h>
#include <cstdint>

// Problem constants (fixed by the reference)
#define M_ITEMS 100000
#define N_USERS 50000
#define DIM     64
#define NB      (M_ITEMS * DIM)   // 6,400,000 floats
#define NU      (N_USERS * DIM)   // 3,200,000 floats
#define E_II_MAX 3200000

#define SCAN_CHUNK  1024
#define SCAN_BLOCKS ((M_ITEMS + SCAN_CHUNK - 1) / SCAN_CHUNK)  // 98

// Static device scratch (no allocations allowed).
// Half layer buffers stored as uint2 (4 halves = one 8B gather unit per lane16).
__device__ uint2 g_h0[NB / 4];          // half layer buffer (emb, then e2)
__device__ uint2 g_h1[NB / 4];          // half layer buffer (e1)
__device__ float g_sum[NB];             // running fp32 sum of layer embeddings
__device__ float g_users[NU];           // all_users (only batch rows are zeroed/used)
__device__ int   g_cnt[M_ITEMS];        // per-row counts (zeroed by k_scan_final each run)
__device__ int   g_rowptr[M_ITEMS + 1]; // CSR row pointers
__device__ int   g_pos[M_ITEMS];        // scatter fill cursors
__device__ int2  g_epack[E_II_MAX];     // CSR: packed (dst, val-bits) per edge
__device__ int   g_part[SCAN_BLOCKS];   // scan partials
__device__ unsigned char g_uflag[N_USERS]; // batch-user flags (set-only, idempotent)

// Vector reduction-add to global (sm_90+)
__device__ __forceinline__ void red_add_f4(float4* addr, float4 v) {
    asm volatile("red.global.add.v4.f32 [%0], {%1, %2, %3, %4};"
                 :: "l"(addr), "f"(v.x), "f"(v.y), "f"(v.z), "f"(v.w)
                 : "memory");
}

// Fused: g_sum = emb (fp32), g_h0 = half(emb) [vectorized], histogram of ii_src.
// g_cnt is zero on entry: static zero-init on first run, re-zeroed by k_scan_final.
__global__ void k_pre(const float* __restrict__ emb, const int* __restrict__ src, int ne) {
    int i = blockIdx.x * blockDim.x + threadIdx.x;
    if (i < NB / 8) {
        const float4* e4 = (const float4*)emb;
        float4 a = __ldg(e4 + 2 * i);
        float4 b = __ldg(e4 + 2 * i + 1);
        ((float4*)g_sum)[2 * i]     = a;
        ((float4*)g_sum)[2 * i + 1] = b;
        __half2 h0 = __floats2half2_rn(a.x, a.y);
        __half2 h1 = __floats2half2_rn(a.z, a.w);
        __half2 h2 = __floats2half2_rn(b.x, b.y);
        __half2 h3 = __floats2half2_rn(b.z, b.w);
        uint4 hp;
        hp.x = *reinterpret_cast<unsigned int*>(&h0);
        hp.y = *reinterpret_cast<unsigned int*>(&h1);
        hp.z = *reinterpret_cast<unsigned int*>(&h2);
        hp.w = *reinterpret_cast<unsigned int*>(&h3);
        ((uint4*)g_h0)[i] = hp;
    }
    if (i < ne) atomicAdd(&g_cnt[__ldg(src + i)], 1);
}

// Flag batch users + zero exactly their g_users rows (16 threads/user, 1 float4 each).
__global__ void k_flag_zero(const int* __restrict__ users, int nusers) {
    int t = blockIdx.x * blockDim.x + threadIdx.x;
    int b = t >> 4;
    int l = t & 15;
    if (b >= nusers) return;
    int u = __ldg(users + b);
    if (l == 0) g_uflag[u] = 1;
    ((float4*)g_users)[(long)u * 16 + l] = make_float4(0.f, 0.f, 0.f, 0.f);
}

// pass 1: per-1024-chunk sums
__global__ void k_scan_part() {
    __shared__ int s[256];
    int tid  = threadIdx.x;
    int base = blockIdx.x * SCAN_CHUNK;
    int sum = 0;
    #pragma unroll
    for (int i = 0; i < 4; i++) {
        int idx = base + tid + i * 256;
        if (idx < M_ITEMS) sum += g_cnt[idx];
    }
    s[tid] = sum;
    __syncthreads();
    for (int off = 128; off; off >>= 1) {
        if (tid < off) s[tid] += s[tid + off];
        __syncthreads();
    }
    if (tid == 0) g_part[blockIdx.x] = s[0];
}

// pass 2 (fused top+final): every block scans the 98 partials itself, then its
// local exclusive scan; writes rowptr/pos and zeroes g_cnt for the next replay.
__global__ void k_scan_final() {
    __shared__ int s[256];
    __shared__ int spart[128];
    int tid = threadIdx.x;

    if (tid < 128) spart[tid] = (tid < SCAN_BLOCKS) ? g_part[tid] : 0;
    __syncthreads();
    for (int off = 1; off < 128; off <<= 1) {
        int t = (tid < 128 && tid >= off) ? spart[tid - off] : 0;
        __syncthreads();
        if (tid < 128) spart[tid] += t;
        __syncthreads();
    }
    int blockOff = (blockIdx.x == 0) ? 0 : spart[blockIdx.x - 1];

    int idx0 = blockIdx.x * SCAN_CHUNK + tid * 4;
    int c[4];
    #pragma unroll
    for (int i = 0; i < 4; i++) {
        int idx = idx0 + i;
        c[i] = (idx < M_ITEMS) ? g_cnt[idx] : 0;
    }
    s[tid] = c[0] + c[1] + c[2] + c[3];
    __syncthreads();
    for (int off = 1; off < 256; off <<= 1) {
        int t = (tid >= off) ? s[tid - off] : 0;
        __syncthreads();
        s[tid] += t;
        __syncthreads();
    }
    int run = blockOff + ((tid == 0) ? 0 : s[tid - 1]);
    #pragma unroll
    for (int i = 0; i < 4; i++) {
        int idx = idx0 + i;
        if (idx < M_ITEMS) {
            g_rowptr[idx] = run;
            g_pos[idx]    = run;
            g_cnt[idx]    = 0;        // reset for next graph replay
            run += c[i];
        }
    }
    if (blockIdx.x == SCAN_BLOCKS - 1 && tid == 0)
        g_rowptr[M_ITEMS] = spart[SCAN_BLOCKS - 1];
}

// scatter edges into CSR order, 4 independent edges per thread (MLP=4 on the
// atomicAdd->store chains).
__global__ void k_scatter(const int* __restrict__ src, const int* __restrict__ dst,
                          const float* __restrict__ val, int n) {
    int i = blockIdx.x * blockDim.x + threadIdx.x;
    int Q = (n + 3) >> 2;
    if (i >= Q) return;
    int e[4]; int s[4]; int2 dv[4]; int p[4];
    #pragma unroll
    for (int k = 0; k < 4; k++) {
        e[k] = i + k * Q;
        if (e[k] < n) {
            s[k]  = __ldg(src + e[k]);
            dv[k] = make_int2(__ldg(dst + e[k]), __float_as_int(__ldg(val + e[k])));
        }
    }
    #pragma unroll
    for (int k = 0; k < 4; k++)
        if (e[k] < n) p[k] = atomicAdd(&g_pos[s[k]], 1);
    #pragma unroll
    for (int k = 0; k < 4; k++)
        if (e[k] < n) g_epack[p[k]] = dv[k];
}

// Pull SpMM, one warp per row, TWO edges per iteration (16 lanes/edge), 8B/lane.
// unroll 8 -> 8 gathers in flight per thread (latency-bound regime needs MLP).
// fp32 accumulation; final cross-half combine via shfl_xor(16).
__global__ void k_spmm_pull(const uint2* __restrict__ x, uint2* __restrict__ yh,
                            const float* __restrict__ att, int layer) {
    int row  = blockIdx.x * (blockDim.x >> 5) + (threadIdx.x >> 5);
    int lane = threadIdx.x & 31;
    if (row >= M_ITEMS) return;
    int lane16 = lane & 15;
    int sub    = lane >> 4;

    int beg = g_rowptr[row];
    int end = g_rowptr[row + 1];

    float4 acc = make_float4(0.0f, 0.0f, 0.0f, 0.0f);
    #pragma unroll 8
    for (int e = beg; e < end; e += 2) {
        int  idx = e + sub;
        bool ok  = idx < end;
        int2 ed  = __ldg(&g_epack[ok ? idx : beg]);
        float v  = ok ? __int_as_float(ed.y) : 0.0f;
        uint2 raw = __ldg(x + (long)ed.x * 16 + lane16);
        float2 f0 = __half22float2(*reinterpret_cast<__half2*>(&raw.x));
        float2 f1 = __half22float2(*reinterpret_cast<__half2*>(&raw.y));
        acc.x = fmaf(v, f0.x, acc.x);
        acc.y = fmaf(v, f0.y, acc.y);
        acc.z = fmaf(v, f1.x, acc.z);
        acc.w = fmaf(v, f1.y, acc.w);
    }
    acc.x += __shfl_xor_sync(0xFFFFFFFFu, acc.x, 16);
    acc.y += __shfl_xor_sync(0xFFFFFFFFu, acc.y, 16);
    acc.z += __shfl_xor_sync(0xFFFFFFFFu, acc.z, 16);
    acc.w += __shfl_xor_sync(0xFFFFFFFFu, acc.w, 16);

    if (sub == 0) {
        float a = __ldg(att + layer);
        acc.x *= a; acc.y *= a; acc.z *= a; acc.w *= a;
        long o = (long)row * 16 + lane16;
        if (yh) {
            __half2 p0 = __floats2half2_rn(acc.x, acc.y);
            __half2 p1 = __floats2half2_rn(acc.z, acc.w);
            uint2 hp;
            hp.x = *reinterpret_cast<unsigned int*>(&p0);
            hp.y = *reinterpret_cast<unsigned int*>(&p1);
            yh[o] = hp;
        }
        float4* sp = (float4*)g_sum + o;
        float4 sv = *sp;
        sv.x += acc.x; sv.y += acc.y; sv.z += acc.z; sv.w += acc.w;
        *sp = sv;
    }
}

// user-item push SpMM, filtered to batch users (fp32 exact):
// g_users[src] += (val * 0.25) * g_sum[dst]
__global__ void k_spmm_ui(const int* __restrict__ src, const int* __restrict__ dst,
                          const float* __restrict__ val, int nedges) {
    long t = (long)blockIdx.x * blockDim.x + threadIdx.x;
    int e    = (int)(t >> 4);
    int lane = (int)(t & 15);
    if (e >= nedges) return;

    int s = __ldg(src + e);
    if (!g_uflag[s]) return;  // ~92% of edges exit here

    int   d = __ldg(dst + e);
    float v = __ldg(val + e) * 0.25f;

    float4 xv = __ldg((const float4*)g_sum + (long)d * 16 + lane);
    float4 r  = make_float4(xv.x * v, xv.y * v, xv.z * v, xv.w * v);
    red_add_f4((float4*)g_users + (long)s * 16 + lane, r);
}

// gamma[b] = dot(g_users[u], 0.25 * g_sum[i]); one warp per pair
__global__ void k_dot(const int* __restrict__ users, const int* __restrict__ items,
                      float* __restrict__ out, int nb) {
    int w    = (blockIdx.x * blockDim.x + threadIdx.x) >> 5;
    int lane = threadIdx.x & 31;
    if (w >= nb) return;

    int u = __ldg(users + w);
    int i = __ldg(items + w);

    float2 a = __ldg((const float2*)g_users + (long)u * 32 + lane);
    float2 b = __ldg((const float2*)g_sum   + (long)i * 32 + lane);
    float p = a.x * b.x + a.y * b.y;

    #pragma unroll
    for (int o = 16; o; o >>= 1) p += __shfl_xor_sync(0xFFFFFFFFu, p, o);

    if (lane == 0) out[w] = 0.25f * p;
}

extern "C" void kernel_launch(void* const* d_in, const int* in_sizes, int n_in,
                              void* d_out, int out_size) {
    const int*   users  = (const int*)d_in[0];
    const int*   items  = (const int*)d_in[1];
    const int*   ii_src = (const int*)d_in[2];
    const int*   ii_dst = (const int*)d_in[3];
    const float* ii_val = (const float*)d_in[4];
    const int*   ui_src = (const int*)d_in[5];
    const int*   ui_dst = (const int*)d_in[6];
    const float* ui_val = (const float*)d_in[7];
    const float* emb    = (const float*)d_in[8];
    const float* att    = (const float*)d_in[9];

    const int Eii = in_sizes[2];
    const int Eui = in_sizes[5];
    const int Bp  = in_sizes[0];

    const int TPB = 256;
    int preN = (NB / 8 > Eii) ? NB / 8 : Eii;
    const int preGrid  = (preN + TPB - 1) / TPB;
    const int scatGrid = (((Eii + 3) >> 2) + TPB - 1) / TPB;
    const int uiGrid   = (int)(((long)Eui * 16 + TPB - 1) / TPB);
    const int rowGrid  = (M_ITEMS + (TPB / 32) - 1) / (TPB / 32);

    uint2 *h0, *h1;
    cudaGetSymbolAddress((void**)&h0, g_h0);
    cudaGetSymbolAddress((void**)&h1, g_h1);

    // 0: fused init (sum/h0) + histogram;  1: flag + zero batch-user rows
    k_pre<<<preGrid, TPB>>>(emb, ii_src, Eii);
    k_flag_zero<<<(Bp * 16 + TPB - 1) / TPB, TPB>>>(users, Bp);
    // 2-3: scan
    k_scan_part <<<SCAN_BLOCKS, 256>>>();
    k_scan_final<<<SCAN_BLOCKS, 256>>>();
    // 4: scatter into CSR, 4 edges/thread
    k_scatter<<<scatGrid, TPB>>>(ii_src, ii_dst, ii_val, Eii);

    // 5-7: pull-based LightGCN layers (sum fused, fp32 acc over half operands)
    k_spmm_pull<<<rowGrid, TPB>>>(h0, h1,      att, 0);  // emb -> e1
    k_spmm_pull<<<rowGrid, TPB>>>(h1, h0,      att, 1);  // e1  -> e2
    k_spmm_pull<<<rowGrid, TPB>>>(h0, nullptr, att, 2);  // e2  -> (sum only)

    // 8: user aggregation, filtered to batch users (0.25 mean folded in)
    k_spmm_ui<<<uiGrid, TPB>>>(ui_src, ui_dst, ui_val, Eui);

    // 9: final per-pair dots
    k_dot<<<(Bp * 32 + TPB - 1) / TPB, TPB>>>(users, items, (float*)d_out, Bp);
}

// round 10
// speedup vs baseline: 1.0576x; 1.0327x over previous
#include <cuda_runtime.h>
#include <cuda_fp16.h>
#include <cstdint>

// Problem constants (fixed by the reference)
#define M_ITEMS 100000
#define N_USERS 50000
#define DIM     64
#define NB      (M_ITEMS * DIM)   // 6,400,000 floats
#define NU      (N_USERS * DIM)   // 3,200,000 floats
#define E_II_MAX 3200000

#define SCAN_CHUNK  1024
#define SCAN_BLOCKS ((M_ITEMS + SCAN_CHUNK - 1) / SCAN_CHUNK)  // 98

// Static device scratch (no allocations allowed).
__device__ uint2 g_h0[NB / 4];          // half layer buffer (emb, then e2)
__device__ uint2 g_h1[NB / 4];          // half layer buffer (e1)
__device__ float g_sum[NB];             // running fp32 sum of layer embeddings
__device__ float g_users[NU];           // all_users (only batch rows zeroed/used)
__device__ int   g_cnt[M_ITEMS];        // per-row counts (re-zeroed by k_scan)
__device__ int   g_rowptr[M_ITEMS + 1]; // CSR row pointers
__device__ int   g_pos[M_ITEMS];        // scatter fill cursors
__device__ int2  g_epack[E_II_MAX];     // CSR: packed (dst, val-bits) per edge
__device__ int   g_sync[SCAN_BLOCKS];   // lookback: aggregate+1, 0 = not ready
__device__ unsigned char g_uflag[N_USERS]; // batch-user flags (set-only, idempotent)

// Vector reduction-add to global (sm_90+)
__device__ __forceinline__ void red_add_f4(float4* addr, float4 v) {
    asm volatile("red.global.add.v4.f32 [%0], {%1, %2, %3, %4};"
                 :: "l"(addr), "f"(v.x), "f"(v.y), "f"(v.z), "f"(v.w)
                 : "memory");
}

__device__ __forceinline__ int block_reduce_sum(int v, int* sw) {
    #pragma unroll
    for (int o = 16; o; o >>= 1) v += __shfl_xor_sync(0xFFFFFFFFu, v, o);
    int w = threadIdx.x >> 5;
    if ((threadIdx.x & 31) == 0) sw[w] = v;
    __syncthreads();
    if (threadIdx.x < 8) {
        v = sw[threadIdx.x];
        #pragma unroll
        for (int o = 4; o; o >>= 1) v += __shfl_xor_sync(0xFFu, v, o);
        if (threadIdx.x == 0) sw[0] = v;
    }
    __syncthreads();
    int r = sw[0];
    __syncthreads();
    return r;
}

// Fused: g_sum = emb (fp32), g_h0 = half(emb) [vectorized], histogram of ii_src,
// zero the scan sync flags. g_cnt is zero on entry (static init / k_scan reset).
__global__ void k_pre(const float* __restrict__ emb, const int* __restrict__ src, int ne) {
    int i = blockIdx.x * blockDim.x + threadIdx.x;
    if (i < NB / 8) {
        const float4* e4 = (const float4*)emb;
        float4 a = __ldg(e4 + 2 * i);
        float4 b = __ldg(e4 + 2 * i + 1);
        ((float4*)g_sum)[2 * i]     = a;
        ((float4*)g_sum)[2 * i + 1] = b;
        __half2 h0 = __floats2half2_rn(a.x, a.y);
        __half2 h1 = __floats2half2_rn(a.z, a.w);
        __half2 h2 = __floats2half2_rn(b.x, b.y);
        __half2 h3 = __floats2half2_rn(b.z, b.w);
        uint4 hp;
        hp.x = *reinterpret_cast<unsigned int*>(&h0);
        hp.y = *reinterpret_cast<unsigned int*>(&h1);
        hp.z = *reinterpret_cast<unsigned int*>(&h2);
        hp.w = *reinterpret_cast<unsigned int*>(&h3);
        ((uint4*)g_h0)[i] = hp;
    }
    if (i < SCAN_BLOCKS) g_sync[i] = 0;
    if (i < ne) atomicAdd(&g_cnt[__ldg(src + i)], 1);
}

// Single-kernel exclusive scan with decoupled lookback.
// 98 blocks, all co-resident on 148 SMs -> spin-wait is deadlock-free.
// Publishes (aggregate+1) in one word; polls predecessors warp-parallel.
// Also re-zeroes g_cnt and fills g_pos.
__global__ void k_scan() {
    __shared__ int s[256];
    __shared__ int sw[8];
    int tid = threadIdx.x, b = blockIdx.x;

    int idx0 = b * SCAN_CHUNK + tid * 4;
    int c[4];
    #pragma unroll
    for (int i = 0; i < 4; i++) {
        int idx = idx0 + i;
        c[i] = (idx < M_ITEMS) ? g_cnt[idx] : 0;
    }
    int t4 = c[0] + c[1] + c[2] + c[3];

    // publish this block's aggregate ASAP
    int agg = block_reduce_sum(t4, sw);
    if (tid == 0) atomicExch(&g_sync[b], agg + 1);

    // lookback: thread t polls predecessor t (b <= 98 <= 256 threads)
    int pre = 0;
    if (tid < b) {
        int v;
        do { v = atomicAdd(&g_sync[tid], 0); } while (v == 0);
        pre = v - 1;
    }
    int blockOff = block_reduce_sum(pre, sw);

    // local exclusive scan of per-thread sums
    s[tid] = t4;
    __syncthreads();
    for (int off = 1; off < 256; off <<= 1) {
        int t = (tid >= off) ? s[tid - off] : 0;
        __syncthreads();
        s[tid] += t;
        __syncthreads();
    }
    int run = blockOff + ((tid == 0) ? 0 : s[tid - 1]);
    #pragma unroll
    for (int i = 0; i < 4; i++) {
        int idx = idx0 + i;
        if (idx < M_ITEMS) {
            g_rowptr[idx] = run;
            g_pos[idx]    = run;
            g_cnt[idx]    = 0;        // reset for next graph replay
            run += c[i];
        }
    }
    if (b == SCAN_BLOCKS - 1 && tid == 255) g_rowptr[M_ITEMS] = run;
}

// scatter edges into CSR order, 4 independent edges per thread (MLP=4 on the
// atomicAdd->store chains).
__global__ void k_scatter(const int* __restrict__ src, const int* __restrict__ dst,
                          const float* __restrict__ val, int n) {
    int i = blockIdx.x * blockDim.x + threadIdx.x;
    int Q = (n + 3) >> 2;
    if (i >= Q) return;
    int e[4]; int s[4]; int2 dv[4]; int p[4];
    #pragma unroll
    for (int k = 0; k < 4; k++) {
        e[k] = i + k * Q;
        if (e[k] < n) {
            s[k]  = __ldg(src + e[k]);
            dv[k] = make_int2(__ldg(dst + e[k]), __float_as_int(__ldg(val + e[k])));
        }
    }
    #pragma unroll
    for (int k = 0; k < 4; k++)
        if (e[k] < n) p[k] = atomicAdd(&g_pos[s[k]], 1);
    #pragma unroll
    for (int k = 0; k < 4; k++)
        if (e[k] < n) g_epack[p[k]] = dv[k];
}

// Pull SpMM, one warp per row, TWO edges per iteration (16 lanes/edge), 8B/lane.
// unroll 4: avg row = 16 two-edge steps -> body covers most work (unroll 8 pushed
// the majority into the MLP=1 remainder loop; measured regression R9).
__global__ void k_spmm_pull(const uint2* __restrict__ x, uint2* __restrict__ yh,
                            const float* __restrict__ att, int layer) {
    int row  = blockIdx.x * (blockDim.x >> 5) + (threadIdx.x >> 5);
    int lane = threadIdx.x & 31;
    if (row >= M_ITEMS) return;
    int lane16 = lane & 15;
    int sub    = lane >> 4;

    int beg = g_rowptr[row];
    int end = g_rowptr[row + 1];

    float4 acc = make_float4(0.0f, 0.0f, 0.0f, 0.0f);
    #pragma unroll 4
    for (int e = beg; e < end; e += 2) {
        int  idx = e + sub;
        bool ok  = idx < end;
        int2 ed  = __ldg(&g_epack[ok ? idx : beg]);
        float v  = ok ? __int_as_float(ed.y) : 0.0f;
        uint2 raw = __ldg(x + (long)ed.x * 16 + lane16);
        float2 f0 = __half22float2(*reinterpret_cast<__half2*>(&raw.x));
        float2 f1 = __half22float2(*reinterpret_cast<__half2*>(&raw.y));
        acc.x = fmaf(v, f0.x, acc.x);
        acc.y = fmaf(v, f0.y, acc.y);
        acc.z = fmaf(v, f1.x, acc.z);
        acc.w = fmaf(v, f1.y, acc.w);
    }
    acc.x += __shfl_xor_sync(0xFFFFFFFFu, acc.x, 16);
    acc.y += __shfl_xor_sync(0xFFFFFFFFu, acc.y, 16);
    acc.z += __shfl_xor_sync(0xFFFFFFFFu, acc.z, 16);
    acc.w += __shfl_xor_sync(0xFFFFFFFFu, acc.w, 16);

    if (sub == 0) {
        float a = __ldg(att + layer);
        acc.x *= a; acc.y *= a; acc.z *= a; acc.w *= a;
        long o = (long)row * 16 + lane16;
        if (yh) {
            __half2 p0 = __floats2half2_rn(acc.x, acc.y);
            __half2 p1 = __floats2half2_rn(acc.z, acc.w);
            uint2 hp;
            hp.x = *reinterpret_cast<unsigned int*>(&p0);
            hp.y = *reinterpret_cast<unsigned int*>(&p1);
            yh[o] = hp;
        }
        float4* sp = (float4*)g_sum + o;
        float4 sv = *sp;
        sv.x += acc.x; sv.y += acc.y; sv.z += acc.z; sv.w += acc.w;
        *sp = sv;
    }
}

// Flag batch users + zero exactly their g_users rows (16 threads/user).
__global__ void k_flag_zero(const int* __restrict__ users, int nusers) {
    int t = blockIdx.x * blockDim.x + threadIdx.x;
    int b = t >> 4;
    int l = t & 15;
    if (b >= nusers) return;
    int u = __ldg(users + b);
    if (l == 0) g_uflag[u] = 1;
    ((float4*)g_users)[(long)u * 16 + l] = make_float4(0.f, 0.f, 0.f, 0.f);
}

// user-item push SpMM, filtered to batch users (fp32 exact):
// g_users[src] += (val * 0.25) * g_sum[dst]
__global__ void k_spmm_ui(const int* __restrict__ src, const int* __restrict__ dst,
                          const float* __restrict__ val, int nedges) {
    long t = (long)blockIdx.x * blockDim.x + threadIdx.x;
    int e    = (int)(t >> 4);
    int lane = (int)(t & 15);
    if (e >= nedges) return;

    int s = __ldg(src + e);
    if (!g_uflag[s]) return;  // ~92% of edges exit here

    int   d = __ldg(dst + e);
    float v = __ldg(val + e) * 0.25f;

    float4 xv = __ldg((const float4*)g_sum + (long)d * 16 + lane);
    float4 r  = make_float4(xv.x * v, xv.y * v, xv.z * v, xv.w * v);
    red_add_f4((float4*)g_users + (long)s * 16 + lane, r);
}

// gamma[b] = dot(g_users[u], 0.25 * g_sum[i]); one warp per pair
__global__ void k_dot(const int* __restrict__ users, const int* __restrict__ items,
                      float* __restrict__ out, int nb) {
    int w    = (blockIdx.x * blockDim.x + threadIdx.x) >> 5;
    int lane = threadIdx.x & 31;
    if (w >= nb) return;

    int u = __ldg(users + w);
    int i = __ldg(items + w);

    float2 a = __ldg((const float2*)g_users + (long)u * 32 + lane);
    float2 b = __ldg((const float2*)g_sum   + (long)i * 32 + lane);
    float p = a.x * b.x + a.y * b.y;

    #pragma unroll
    for (int o = 16; o; o >>= 1) p += __shfl_xor_sync(0xFFFFFFFFu, p, o);

    if (lane == 0) out[w] = 0.25f * p;
}

extern "C" void kernel_launch(void* const* d_in, const int* in_sizes, int n_in,
                              void* d_out, int out_size) {
    const int*   users  = (const int*)d_in[0];
    const int*   items  = (const int*)d_in[1];
    const int*   ii_src = (const int*)d_in[2];
    const int*   ii_dst = (const int*)d_in[3];
    const float* ii_val = (const float*)d_in[4];
    const int*   ui_src = (const int*)d_in[5];
    const int*   ui_dst = (const int*)d_in[6];
    const float* ui_val = (const float*)d_in[7];
    const float* emb    = (const float*)d_in[8];
    const float* att    = (const float*)d_in[9];

    const int Eii = in_sizes[2];
    const int Eui = in_sizes[5];
    const int Bp  = in_sizes[0];

    const int TPB = 256;
    int preN = (NB / 8 > Eii) ? NB / 8 : Eii;
    const int preGrid  = (preN + TPB - 1) / TPB;
    const int scatGrid = (((Eii + 3) >> 2) + TPB - 1) / TPB;
    const int uiGrid   = (int)(((long)Eui * 16 + TPB - 1) / TPB);
    const int rowGrid  = (M_ITEMS + (TPB / 32) - 1) / (TPB / 32);

    uint2 *h0, *h1;
    cudaGetSymbolAddress((void**)&h0, g_h0);
    cudaGetSymbolAddress((void**)&h1, g_h1);

    // 0: fused init (sum/h0) + histogram + sync reset
    k_pre<<<preGrid, TPB>>>(emb, ii_src, Eii);
    // 1: single-kernel lookback scan (writes rowptr/pos, zeroes cnt)
    k_scan<<<SCAN_BLOCKS, 256>>>();
    // 2: scatter into CSR, 4 edges/thread
    k_scatter<<<scatGrid, TPB>>>(ii_src, ii_dst, ii_val, Eii);

    // 3-5: pull-based LightGCN layers (idx 3 = profiled launch)
    k_spmm_pull<<<rowGrid, TPB>>>(h0, h1,      att, 0);  // emb -> e1
    k_spmm_pull<<<rowGrid, TPB>>>(h1, h0,      att, 1);  // e1  -> e2
    k_spmm_pull<<<rowGrid, TPB>>>(h0, nullptr, att, 2);  // e2  -> (sum only)

    // 6: flag batch users + zero their rows (needed only before ui)
    k_flag_zero<<<(Bp * 16 + TPB - 1) / TPB, TPB>>>(users, Bp);
    // 7: user aggregation, filtered to batch users (0.25 mean folded in)
    k_spmm_ui<<<uiGrid, TPB>>>(ui_src, ui_dst, ui_val, Eui);
    // 8: final per-pair dots
    k_dot<<<(Bp * 32 + TPB - 1) / TPB, TPB>>>(users, items, (float*)d_out, Bp);
}

// round 11
// speedup vs baseline: 1.1635x; 1.1001x over previous
#include <cuda_runtime.h>
#include <cuda_fp16.h>
#include <cstdint>

// Problem constants (fixed by the reference)
#define M_ITEMS 100000
#define N_USERS 50000
#define DIM     64
#define NB      (M_ITEMS * DIM)   // 6,400,000 floats
#define NU      (N_USERS * DIM)   // 3,200,000 floats
#define E_II_MAX 3200000
#define E_UI_MAX 1600000

#define SCAN_CHUNK  1024
#define SCAN_BLOCKS ((M_ITEMS + SCAN_CHUNK - 1) / SCAN_CHUNK)  // 98

// Static device scratch (no allocations allowed).
__device__ uint2 g_h0[NB / 4];          // half layer buffer (emb, then e2)
__device__ uint2 g_h1[NB / 4];          // half layer buffer (e1)
__device__ float g_sum[NB];             // running fp32 sum of layer embeddings
__device__ float g_users[NU];           // all_users (only batch rows zeroed/used)
__device__ int   g_cnt[M_ITEMS];        // per-row counts (re-zeroed by k_scan)
__device__ int   g_rowptr[M_ITEMS + 1]; // CSR row pointers
__device__ int   g_pos[M_ITEMS];        // scatter fill cursors
__device__ int2  g_epack[E_II_MAX];     // CSR: (dst*16, val-bits) per edge
__device__ int   g_sync[SCAN_BLOCKS];   // lookback: aggregate+1, 0 = not ready
__device__ unsigned char g_uflag[N_USERS]; // batch-user flags (set-only, idempotent)
__device__ int   g_uecnt;               // compacted ui-edge count (reset in k_pre)
__device__ int4  g_ue4[E_UI_MAX];       // compacted ui edges: (u*16, i*16, valbits, -)

// Vector reduction-add to global (sm_90+)
__device__ __forceinline__ void red_add_f4(float4* addr, float4 v) {
    asm volatile("red.global.add.v4.f32 [%0], {%1, %2, %3, %4};"
                 :: "l"(addr), "f"(v.x), "f"(v.y), "f"(v.z), "f"(v.w)
                 : "memory");
}

__device__ __forceinline__ int block_reduce_sum(int v, int* sw) {
    #pragma unroll
    for (int o = 16; o; o >>= 1) v += __shfl_xor_sync(0xFFFFFFFFu, v, o);
    int w = threadIdx.x >> 5;
    if ((threadIdx.x & 31) == 0) sw[w] = v;
    __syncthreads();
    if (threadIdx.x < 8) {
        v = sw[threadIdx.x];
        #pragma unroll
        for (int o = 4; o; o >>= 1) v += __shfl_xor_sync(0xFFu, v, o);
        if (threadIdx.x == 0) sw[0] = v;
    }
    __syncthreads();
    int r = sw[0];
    __syncthreads();
    return r;
}

// Fused: g_sum = emb (fp32), g_h0 = half(emb), histogram of ii_src,
// zero scan sync flags + ui edge counter.
__global__ void k_pre(const float* __restrict__ emb, const int* __restrict__ src, int ne) {
    int i = blockIdx.x * blockDim.x + threadIdx.x;
    if (i < NB / 8) {
        const float4* e4 = (const float4*)emb;
        float4 a = __ldg(e4 + 2 * i);
        float4 b = __ldg(e4 + 2 * i + 1);
        ((float4*)g_sum)[2 * i]     = a;
        ((float4*)g_sum)[2 * i + 1] = b;
        __half2 h0 = __floats2half2_rn(a.x, a.y);
        __half2 h1 = __floats2half2_rn(a.z, a.w);
        __half2 h2 = __floats2half2_rn(b.x, b.y);
        __half2 h3 = __floats2half2_rn(b.z, b.w);
        uint4 hp;
        hp.x = *reinterpret_cast<unsigned int*>(&h0);
        hp.y = *reinterpret_cast<unsigned int*>(&h1);
        hp.z = *reinterpret_cast<unsigned int*>(&h2);
        hp.w = *reinterpret_cast<unsigned int*>(&h3);
        ((uint4*)g_h0)[i] = hp;
    }
    if (i < SCAN_BLOCKS) g_sync[i] = 0;
    if (i == 0) g_uecnt = 0;
    if (i < ne) atomicAdd(&g_cnt[__ldg(src + i)], 1);
}

// Single-kernel exclusive scan with decoupled lookback (98 co-resident blocks).
__global__ void k_scan() {
    __shared__ int s[256];
    __shared__ int sw[8];
    int tid = threadIdx.x, b = blockIdx.x;

    int idx0 = b * SCAN_CHUNK + tid * 4;
    int c[4];
    #pragma unroll
    for (int i = 0; i < 4; i++) {
        int idx = idx0 + i;
        c[i] = (idx < M_ITEMS) ? g_cnt[idx] : 0;
    }
    int t4 = c[0] + c[1] + c[2] + c[3];

    int agg = block_reduce_sum(t4, sw);
    if (tid == 0) atomicExch(&g_sync[b], agg + 1);

    int pre = 0;
    if (tid < b) {
        int v;
        do { v = atomicAdd(&g_sync[tid], 0); } while (v == 0);
        pre = v - 1;
    }
    int blockOff = block_reduce_sum(pre, sw);

    s[tid] = t4;
    __syncthreads();
    for (int off = 1; off < 256; off <<= 1) {
        int t = (tid >= off) ? s[tid - off] : 0;
        __syncthreads();
        s[tid] += t;
        __syncthreads();
    }
    int run = blockOff + ((tid == 0) ? 0 : s[tid - 1]);
    #pragma unroll
    for (int i = 0; i < 4; i++) {
        int idx = idx0 + i;
        if (idx < M_ITEMS) {
            g_rowptr[idx] = run;
            g_pos[idx]    = run;
            g_cnt[idx]    = 0;
            run += c[i];
        }
    }
    if (b == SCAN_BLOCKS - 1 && tid == 255) g_rowptr[M_ITEMS] = run;
}

// scatter edges into CSR order, 8 independent edges per thread (MLP=8).
// Stores dst PREMULTIPLIED by 16 (uint2-row offset) to kill IMADs in spmm.
__global__ void k_scatter(const int* __restrict__ src, const int* __restrict__ dst,
                          const float* __restrict__ val, int n) {
    int i = blockIdx.x * blockDim.x + threadIdx.x;
    int Q = (n + 7) >> 3;
    if (i >= Q) return;
    int e[8]; int s[8]; int2 dv[8]; int p[8];
    #pragma unroll
    for (int k = 0; k < 8; k++) {
        e[k] = i + k * Q;
        if (e[k] < n) {
            s[k]  = __ldg(src + e[k]);
            dv[k] = make_int2(__ldg(dst + e[k]) << 4, __float_as_int(__ldg(val + e[k])));
        }
    }
    #pragma unroll
    for (int k = 0; k < 8; k++)
        if (e[k] < n) p[k] = atomicAdd(&g_pos[s[k]], 1);
    #pragma unroll
    for (int k = 0; k < 8; k++)
        if (e[k] < n) g_epack[p[k]] = dv[k];
}

// Pull SpMM, one warp per row, TWO edges per iteration (16 lanes/edge), 8B/lane.
// Odd edge peeled before the loop -> main loop is predication-free.
// CSR dst is premultiplied by 16 -> gather index = ed.x | lane16 (one LOP3).
__global__ void k_spmm_pull(const uint2* __restrict__ x, uint2* __restrict__ yh,
                            const float* __restrict__ att, int layer) {
    int row  = blockIdx.x * (blockDim.x >> 5) + (threadIdx.x >> 5);
    int lane = threadIdx.x & 31;
    if (row >= M_ITEMS) return;
    int lane16 = lane & 15;
    int sub    = lane >> 4;

    int beg = g_rowptr[row];
    int end = g_rowptr[row + 1];

    float4 acc = make_float4(0.0f, 0.0f, 0.0f, 0.0f);

    if ((end - beg) & 1) {              // peel odd edge (both halves load it;
        int2 ed = __ldg(&g_epack[beg]); //  sub==1 contributes 0)
        float v = (sub == 0) ? __int_as_float(ed.y) : 0.0f;
        uint2 raw = __ldg(x + (unsigned)(ed.x | lane16));
        float2 f0 = __half22float2(*reinterpret_cast<__half2*>(&raw.x));
        float2 f1 = __half22float2(*reinterpret_cast<__half2*>(&raw.y));
        acc.x = fmaf(v, f0.x, acc.x);
        acc.y = fmaf(v, f0.y, acc.y);
        acc.z = fmaf(v, f1.x, acc.z);
        acc.w = fmaf(v, f1.y, acc.w);
        beg++;
    }
    #pragma unroll 4
    for (int e = beg; e < end; e += 2) {
        int2  ed = __ldg(&g_epack[e + sub]);
        float v  = __int_as_float(ed.y);
        uint2 raw = __ldg(x + (unsigned)(ed.x | lane16));
        float2 f0 = __half22float2(*reinterpret_cast<__half2*>(&raw.x));
        float2 f1 = __half22float2(*reinterpret_cast<__half2*>(&raw.y));
        acc.x = fmaf(v, f0.x, acc.x);
        acc.y = fmaf(v, f0.y, acc.y);
        acc.z = fmaf(v, f1.x, acc.z);
        acc.w = fmaf(v, f1.y, acc.w);
    }
    acc.x += __shfl_xor_sync(0xFFFFFFFFu, acc.x, 16);
    acc.y += __shfl_xor_sync(0xFFFFFFFFu, acc.y, 16);
    acc.z += __shfl_xor_sync(0xFFFFFFFFu, acc.z, 16);
    acc.w += __shfl_xor_sync(0xFFFFFFFFu, acc.w, 16);

    if (sub == 0) {
        float a = __ldg(att + layer);
        acc.x *= a; acc.y *= a; acc.z *= a; acc.w *= a;
        unsigned o = (unsigned)row * 16u + lane16;
        if (yh) {
            __half2 p0 = __floats2half2_rn(acc.x, acc.y);
            __half2 p1 = __floats2half2_rn(acc.z, acc.w);
            uint2 hp;
            hp.x = *reinterpret_cast<unsigned int*>(&p0);
            hp.y = *reinterpret_cast<unsigned int*>(&p1);
            yh[o] = hp;
        }
        float4* sp = (float4*)g_sum + o;
        float4 sv = *sp;
        sv.x += acc.x; sv.y += acc.y; sv.z += acc.z; sv.w += acc.w;
        *sp = sv;
    }
}

// Flag batch users + zero exactly their g_users rows (16 threads/user).
__global__ void k_flag_zero(const int* __restrict__ users, int nusers) {
    int t = blockIdx.x * blockDim.x + threadIdx.x;
    int b = t >> 4;
    int l = t & 15;
    if (b >= nusers) return;
    int u = __ldg(users + b);
    if (l == 0) g_uflag[u] = 1;
    ((float4*)g_users)[(long)u * 16 + l] = make_float4(0.f, 0.f, 0.f, 0.f);
}

// ui phase A: compact edges whose user is in the batch into packed records.
// Warp-aggregated counter atomic (nvcc REDUX-aggregates uniform-addr atomicAdd).
__global__ void k_ui_filter(const int* __restrict__ src, const int* __restrict__ dst,
                            const float* __restrict__ val, int nedges) {
    int e = blockIdx.x * blockDim.x + threadIdx.x;
    if (e >= nedges) return;
    int s = __ldg(src + e);
    if (!g_uflag[s]) return;
    int p = atomicAdd(&g_uecnt, 1);
    g_ue4[p] = make_int4(s << 4, __ldg(dst + e) << 4, __float_as_int(__ldg(val + e)), 0);
}

// ui phase B: grid-stride over the compacted list, 2 edges/warp, 16 lanes/edge.
// g_users[u] += (val * 0.25) * g_sum[i]
__global__ void k_ui_gather() {
    int K = g_uecnt;
    int warps = (gridDim.x * blockDim.x) >> 5;
    int w     = (blockIdx.x * blockDim.x + threadIdx.x) >> 5;
    int lane  = threadIdx.x & 31;
    int lane16 = lane & 15;
    int sub    = lane >> 4;

    for (int i = w * 2 + sub; i < K; i += warps * 2) {
        int4 t = __ldg(&g_ue4[i]);
        float v = __int_as_float(t.z) * 0.25f;
        float4 xv = __ldg((const float4*)g_sum + (unsigned)(t.y | lane16));
        float4 r  = make_float4(xv.x * v, xv.y * v, xv.z * v, xv.w * v);
        red_add_f4((float4*)g_users + (unsigned)(t.x | lane16), r);
    }
}

// gamma[b] = dot(g_users[u], 0.25 * g_sum[i]); one warp per pair
__global__ void k_dot(const int* __restrict__ users, const int* __restrict__ items,
                      float* __restrict__ out, int nb) {
    int w    = (blockIdx.x * blockDim.x + threadIdx.x) >> 5;
    int lane = threadIdx.x & 31;
    if (w >= nb) return;

    int u = __ldg(users + w);
    int i = __ldg(items + w);

    float2 a = __ldg((const float2*)g_users + (long)u * 32 + lane);
    float2 b = __ldg((const float2*)g_sum   + (long)i * 32 + lane);
    float p = a.x * b.x + a.y * b.y;

    #pragma unroll
    for (int o = 16; o; o >>= 1) p += __shfl_xor_sync(0xFFFFFFFFu, p, o);

    if (lane == 0) out[w] = 0.25f * p;
}

extern "C" void kernel_launch(void* const* d_in, const int* in_sizes, int n_in,
                              void* d_out, int out_size) {
    const int*   users  = (const int*)d_in[0];
    const int*   items  = (const int*)d_in[1];
    const int*   ii_src = (const int*)d_in[2];
    const int*   ii_dst = (const int*)d_in[3];
    const float* ii_val = (const float*)d_in[4];
    const int*   ui_src = (const int*)d_in[5];
    const int*   ui_dst = (const int*)d_in[6];
    const float* ui_val = (const float*)d_in[7];
    const float* emb    = (const float*)d_in[8];
    const float* att    = (const float*)d_in[9];

    const int Eii = in_sizes[2];
    const int Eui = in_sizes[5];
    const int Bp  = in_sizes[0];

    const int TPB = 256;
    int preN = (NB / 8 > Eii) ? NB / 8 : Eii;
    const int preGrid  = (preN + TPB - 1) / TPB;
    const int scatGrid = (((Eii + 7) >> 3) + TPB - 1) / TPB;
    const int rowGrid  = (M_ITEMS + (TPB / 32) - 1) / (TPB / 32);

    uint2 *h0, *h1;
    cudaGetSymbolAddress((void**)&h0, g_h0);
    cudaGetSymbolAddress((void**)&h1, g_h1);

    // 0: fused init (sum/h0) + histogram + counter resets
    k_pre<<<preGrid, TPB>>>(emb, ii_src, Eii);
    // 1: single-kernel lookback scan (writes rowptr/pos, zeroes cnt)
    k_scan<<<SCAN_BLOCKS, 256>>>();
    // 2: scatter into CSR, 8 edges/thread, dst premultiplied
    k_scatter<<<scatGrid, TPB>>>(ii_src, ii_dst, ii_val, Eii);

    // 3-5: pull-based LightGCN layers (idx 3 = profiled launch)
    k_spmm_pull<<<rowGrid, TPB>>>(h0, h1,      att, 0);  // emb -> e1
    k_spmm_pull<<<rowGrid, TPB>>>(h1, h0,      att, 1);  // e1  -> e2
    k_spmm_pull<<<rowGrid, TPB>>>(h0, nullptr, att, 2);  // e2  -> (sum only)

    // 6: flag batch users + zero their rows
    k_flag_zero<<<(Bp * 16 + TPB - 1) / TPB, TPB>>>(users, Bp);
    // 7: compact batch-user edges;  8: process compacted list
    k_ui_filter<<<(Eui + TPB - 1) / TPB, TPB>>>(ui_src, ui_dst, ui_val, Eui);
    k_ui_gather<<<1184, TPB>>>();
    // 9: final per-pair dots
    k_dot<<<(Bp * 32 + TPB - 1) / TPB, TPB>>>(users, items, (float*)d_out, Bp);
}

// round 12
// speedup vs baseline: 1.1971x; 1.0289x over previous
#include <cuda_runtime.h>
#include <cuda_fp16.h>
#include <cstdint>

// Problem constants (fixed by the reference)
#define M_ITEMS 100000
#define N_USERS 50000
#define DIM     64
#define NB      (M_ITEMS * DIM)   // 6,400,000 floats
#define NU      (N_USERS * DIM)   // 3,200,000 floats
#define E_II_MAX 3200000
#define E_UI_MAX 1600000

#define SCAN_CHUNK  1024
#define SCAN_BLOCKS ((M_ITEMS + SCAN_CHUNK - 1) / SCAN_CHUNK)  // 98

// Static device scratch (no allocations allowed).
__device__ uint2 g_h0[NB / 4];          // half(emb) -> later e3
__device__ uint2 g_h1[NB / 4];          // e1
__device__ uint2 g_h2[NB / 4];          // e2
__device__ float g_sum[NB];             // all_items*4 (built once by k_post)
__device__ float g_users[NU];           // all_users (only batch rows zeroed/used)
__device__ int   g_cnt[M_ITEMS];        // per-row counts (re-zeroed by k_scan)
__device__ int   g_rowptr[M_ITEMS + 1]; // CSR row pointers
__device__ int   g_pos[M_ITEMS];        // scatter fill cursors
__device__ int2  g_epack[E_II_MAX];     // CSR: (dst*16, val-bits) per edge
__device__ int   g_sync[SCAN_BLOCKS];   // lookback: aggregate+1, 0 = not ready
__device__ unsigned char g_uflag[N_USERS]; // batch-user flags (set-only, idempotent)
__device__ int   g_uecnt;               // compacted ui-edge count (reset in k_pre)
__device__ int4  g_ue4[E_UI_MAX];       // compacted ui edges: (u*16, i*16, valbits, -)

// Vector reduction-add to global (sm_90+)
__device__ __forceinline__ void red_add_f4(float4* addr, float4 v) {
    asm volatile("red.global.add.v4.f32 [%0], {%1, %2, %3, %4};"
                 :: "l"(addr), "f"(v.x), "f"(v.y), "f"(v.z), "f"(v.w)
                 : "memory");
}

// Streaming (evict-first) 8B load — keeps the once-read edge stream out of L1's
// way so the row working set stays resident.
__device__ __forceinline__ int2 ldcs_int2(const int2* p) {
    int2 r;
    asm volatile("ld.global.cs.v2.b32 {%0, %1}, [%2];"
                 : "=r"(r.x), "=r"(r.y) : "l"(p));
    return r;
}
__device__ __forceinline__ void stcs_uint2(uint2* p, uint2 v) {
    asm volatile("st.global.cs.v2.b32 [%0], {%1, %2};"
                 :: "l"(p), "r"(v.x), "r"(v.y));
}

__device__ __forceinline__ int block_reduce_sum(int v, int* sw) {
    #pragma unroll
    for (int o = 16; o; o >>= 1) v += __shfl_xor_sync(0xFFFFFFFFu, v, o);
    int w = threadIdx.x >> 5;
    if ((threadIdx.x & 31) == 0) sw[w] = v;
    __syncthreads();
    if (threadIdx.x < 8) {
        v = sw[threadIdx.x];
        #pragma unroll
        for (int o = 4; o; o >>= 1) v += __shfl_xor_sync(0xFFu, v, o);
        if (threadIdx.x == 0) sw[0] = v;
    }
    __syncthreads();
    int r = sw[0];
    __syncthreads();
    return r;
}

// Fused: g_h0 = half(emb), histogram of ii_src, counter resets.
__global__ void k_pre(const float* __restrict__ emb, const int* __restrict__ src, int ne) {
    int i = blockIdx.x * blockDim.x + threadIdx.x;
    if (i < NB / 8) {
        const float4* e4 = (const float4*)emb;
        float4 a = __ldg(e4 + 2 * i);
        float4 b = __ldg(e4 + 2 * i + 1);
        __half2 h0 = __floats2half2_rn(a.x, a.y);
        __half2 h1 = __floats2half2_rn(a.z, a.w);
        __half2 h2 = __floats2half2_rn(b.x, b.y);
        __half2 h3 = __floats2half2_rn(b.z, b.w);
        uint4 hp;
        hp.x = *reinterpret_cast<unsigned int*>(&h0);
        hp.y = *reinterpret_cast<unsigned int*>(&h1);
        hp.z = *reinterpret_cast<unsigned int*>(&h2);
        hp.w = *reinterpret_cast<unsigned int*>(&h3);
        ((uint4*)g_h0)[i] = hp;
    }
    if (i < SCAN_BLOCKS) g_sync[i] = 0;
    if (i == 0) g_uecnt = 0;
    if (i < ne) atomicAdd(&g_cnt[__ldg(src + i)], 1);
}

// Single-kernel exclusive scan with decoupled lookback (98 co-resident blocks).
__global__ void k_scan() {
    __shared__ int s[256];
    __shared__ int sw[8];
    int tid = threadIdx.x, b = blockIdx.x;

    int idx0 = b * SCAN_CHUNK + tid * 4;
    int c[4];
    #pragma unroll
    for (int i = 0; i < 4; i++) {
        int idx = idx0 + i;
        c[i] = (idx < M_ITEMS) ? g_cnt[idx] : 0;
    }
    int t4 = c[0] + c[1] + c[2] + c[3];

    int agg = block_reduce_sum(t4, sw);
    if (tid == 0) atomicExch(&g_sync[b], agg + 1);

    int pre = 0;
    if (tid < b) {
        int v;
        do { v = atomicAdd(&g_sync[tid], 0); } while (v == 0);
        pre = v - 1;
    }
    int blockOff = block_reduce_sum(pre, sw);

    s[tid] = t4;
    __syncthreads();
    for (int off = 1; off < 256; off <<= 1) {
        int t = (tid >= off) ? s[tid - off] : 0;
        __syncthreads();
        s[tid] += t;
        __syncthreads();
    }
    int run = blockOff + ((tid == 0) ? 0 : s[tid - 1]);
    #pragma unroll
    for (int i = 0; i < 4; i++) {
        int idx = idx0 + i;
        if (idx < M_ITEMS) {
            g_rowptr[idx] = run;
            g_pos[idx]    = run;
            g_cnt[idx]    = 0;
            run += c[i];
        }
    }
    if (b == SCAN_BLOCKS - 1 && tid == 255) g_rowptr[M_ITEMS] = run;
}

// scatter edges into CSR order, 8 independent edges per thread (MLP=8).
// Stores dst PREMULTIPLIED by 16 (uint2-row offset).
__global__ void k_scatter(const int* __restrict__ src, const int* __restrict__ dst,
                          const float* __restrict__ val, int n) {
    int i = blockIdx.x * blockDim.x + threadIdx.x;
    int Q = (n + 7) >> 3;
    if (i >= Q) return;
    int e[8]; int s[8]; int2 dv[8]; int p[8];
    #pragma unroll
    for (int k = 0; k < 8; k++) {
        e[k] = i + k * Q;
        if (e[k] < n) {
            s[k]  = __ldg(src + e[k]);
            dv[k] = make_int2(__ldg(dst + e[k]) << 4, __float_as_int(__ldg(val + e[k])));
        }
    }
    #pragma unroll
    for (int k = 0; k < 8; k++)
        if (e[k] < n) p[k] = atomicAdd(&g_pos[s[k]], 1);
    #pragma unroll
    for (int k = 0; k < 8; k++)
        if (e[k] < n) g_epack[p[k]] = dv[k];
}

// Pull SpMM, one warp per row, TWO edges per iteration (16 lanes/edge), 8B/lane.
// Edge records loaded with .cs (streaming), row gathers with .nc (cached).
// Output: half layer buffer only — no fp32 sum RMW (deferred to k_post).
__global__ void k_spmm_pull(const uint2* __restrict__ x, uint2* __restrict__ yh,
                            const float* __restrict__ att, int layer) {
    int row  = blockIdx.x * (blockDim.x >> 5) + (threadIdx.x >> 5);
    int lane = threadIdx.x & 31;
    if (row >= M_ITEMS) return;
    int lane16 = lane & 15;
    int sub    = lane >> 4;

    int beg = g_rowptr[row];
    int end = g_rowptr[row + 1];

    float4 acc = make_float4(0.0f, 0.0f, 0.0f, 0.0f);

    if ((end - beg) & 1) {                    // peel odd edge
        int2 ed = ldcs_int2(&g_epack[beg]);
        float v = (sub == 0) ? __int_as_float(ed.y) : 0.0f;
        uint2 raw = __ldg(x + (unsigned)(ed.x | lane16));
        float2 f0 = __half22float2(*reinterpret_cast<__half2*>(&raw.x));
        float2 f1 = __half22float2(*reinterpret_cast<__half2*>(&raw.y));
        acc.x = fmaf(v, f0.x, acc.x);
        acc.y = fmaf(v, f0.y, acc.y);
        acc.z = fmaf(v, f1.x, acc.z);
        acc.w = fmaf(v, f1.y, acc.w);
        beg++;
    }
    #pragma unroll 4
    for (int e = beg; e < end; e += 2) {
        int2  ed = ldcs_int2(&g_epack[e + sub]);
        float v  = __int_as_float(ed.y);
        uint2 raw = __ldg(x + (unsigned)(ed.x | lane16));
        float2 f0 = __half22float2(*reinterpret_cast<__half2*>(&raw.x));
        float2 f1 = __half22float2(*reinterpret_cast<__half2*>(&raw.y));
        acc.x = fmaf(v, f0.x, acc.x);
        acc.y = fmaf(v, f0.y, acc.y);
        acc.z = fmaf(v, f1.x, acc.z);
        acc.w = fmaf(v, f1.y, acc.w);
    }
    acc.x += __shfl_xor_sync(0xFFFFFFFFu, acc.x, 16);
    acc.y += __shfl_xor_sync(0xFFFFFFFFu, acc.y, 16);
    acc.z += __shfl_xor_sync(0xFFFFFFFFu, acc.z, 16);
    acc.w += __shfl_xor_sync(0xFFFFFFFFu, acc.w, 16);

    if (sub == 0) {
        float a = __ldg(att + layer);
        __half2 p0 = __floats2half2_rn(acc.x * a, acc.y * a);
        __half2 p1 = __floats2half2_rn(acc.z * a, acc.w * a);
        uint2 hp;
        hp.x = *reinterpret_cast<unsigned int*>(&p0);
        hp.y = *reinterpret_cast<unsigned int*>(&p1);
        stcs_uint2(yh + ((unsigned)row * 16u + lane16), hp);
    }
}

// Build g_sum = emb + e1 + e2 + e3 (fp32, halves widened), vectorized.
__global__ void k_post(const float* __restrict__ emb) {
    int i = blockIdx.x * blockDim.x + threadIdx.x;
    if (i >= NB / 8) return;
    const float4* e4 = (const float4*)emb;
    float4 a = __ldg(e4 + 2 * i);
    float4 b = __ldg(e4 + 2 * i + 1);
    uint4 x1 = ((const uint4*)g_h1)[i];
    uint4 x2 = ((const uint4*)g_h2)[i];
    uint4 x3 = ((const uint4*)g_h0)[i];   // e3 overwrote half(emb)
    #pragma unroll
    for (int q = 0; q < 3; q++) {
        uint4 u = (q == 0) ? x1 : (q == 1) ? x2 : x3;
        float2 f0 = __half22float2(*reinterpret_cast<__half2*>(&u.x));
        float2 f1 = __half22float2(*reinterpret_cast<__half2*>(&u.y));
        float2 f2 = __half22float2(*reinterpret_cast<__half2*>(&u.z));
        float2 f3 = __half22float2(*reinterpret_cast<__half2*>(&u.w));
        a.x += f0.x; a.y += f0.y; a.z += f1.x; a.w += f1.y;
        b.x += f2.x; b.y += f2.y; b.z += f3.x; b.w += f3.y;
    }
    ((float4*)g_sum)[2 * i]     = a;
    ((float4*)g_sum)[2 * i + 1] = b;
}

// Flag batch users + zero exactly their g_users rows (16 threads/user).
__global__ void k_flag_zero(const int* __restrict__ users, int nusers) {
    int t = blockIdx.x * blockDim.x + threadIdx.x;
    int b = t >> 4;
    int l = t & 15;
    if (b >= nusers) return;
    int u = __ldg(users + b);
    if (l == 0) g_uflag[u] = 1;
    ((float4*)g_users)[(long)u * 16 + l] = make_float4(0.f, 0.f, 0.f, 0.f);
}

// ui phase A: compact edges whose user is in the batch into packed records.
__global__ void k_ui_filter(const int* __restrict__ src, const int* __restrict__ dst,
                            const float* __restrict__ val, int nedges) {
    int e = blockIdx.x * blockDim.x + threadIdx.x;
    if (e >= nedges) return;
    int s = __ldg(src + e);
    if (!g_uflag[s]) return;
    int p = atomicAdd(&g_uecnt, 1);
    g_ue4[p] = make_int4(s << 4, __ldg(dst + e) << 4, __float_as_int(__ldg(val + e)), 0);
}

// ui phase B: grid-stride over the compacted list, 2 edges/warp, 16 lanes/edge.
__global__ void k_ui_gather() {
    int K = g_uecnt;
    int warps = (gridDim.x * blockDim.x) >> 5;
    int w     = (blockIdx.x * blockDim.x + threadIdx.x) >> 5;
    int lane  = threadIdx.x & 31;
    int lane16 = lane & 15;
    int sub    = lane >> 4;

    for (int i = w * 2 + sub; i < K; i += warps * 2) {
        int4 t = __ldg(&g_ue4[i]);
        float v = __int_as_float(t.z) * 0.25f;
        float4 xv = __ldg((const float4*)g_sum + (unsigned)(t.y | lane16));
        float4 r  = make_float4(xv.x * v, xv.y * v, xv.z * v, xv.w * v);
        red_add_f4((float4*)g_users + (unsigned)(t.x | lane16), r);
    }
}

// gamma[b] = dot(g_users[u], 0.25 * g_sum[i]); one warp per pair
__global__ void k_dot(const int* __restrict__ users, const int* __restrict__ items,
                      float* __restrict__ out, int nb) {
    int w    = (blockIdx.x * blockDim.x + threadIdx.x) >> 5;
    int lane = threadIdx.x & 31;
    if (w >= nb) return;

    int u = __ldg(users + w);
    int i = __ldg(items + w);

    float2 a = __ldg((const float2*)g_users + (long)u * 32 + lane);
    float2 b = __ldg((const float2*)g_sum   + (long)i * 32 + lane);
    float p = a.x * b.x + a.y * b.y;

    #pragma unroll
    for (int o = 16; o; o >>= 1) p += __shfl_xor_sync(0xFFFFFFFFu, p, o);

    if (lane == 0) out[w] = 0.25f * p;
}

extern "C" void kernel_launch(void* const* d_in, const int* in_sizes, int n_in,
                              void* d_out, int out_size) {
    const int*   users  = (const int*)d_in[0];
    const int*   items  = (const int*)d_in[1];
    const int*   ii_src = (const int*)d_in[2];
    const int*   ii_dst = (const int*)d_in[3];
    const float* ii_val = (const float*)d_in[4];
    const int*   ui_src = (const int*)d_in[5];
    const int*   ui_dst = (const int*)d_in[6];
    const float* ui_val = (const float*)d_in[7];
    const float* emb    = (const float*)d_in[8];
    const float* att    = (const float*)d_in[9];

    const int Eii = in_sizes[2];
    const int Eui = in_sizes[5];
    const int Bp  = in_sizes[0];

    const int TPB = 256;
    int preN = (NB / 8 > Eii) ? NB / 8 : Eii;
    const int preGrid  = (preN + TPB - 1) / TPB;
    const int scatGrid = (((Eii + 7) >> 3) + TPB - 1) / TPB;
    const int rowGrid  = (M_ITEMS + (TPB / 32) - 1) / (TPB / 32);
    const int nb8Grid  = (NB / 8 + TPB - 1) / TPB;

    uint2 *h0, *h1, *h2;
    cudaGetSymbolAddress((void**)&h0, g_h0);
    cudaGetSymbolAddress((void**)&h1, g_h1);
    cudaGetSymbolAddress((void**)&h2, g_h2);

    // 0: fused init (h0) + histogram + counter resets
    k_pre<<<preGrid, TPB>>>(emb, ii_src, Eii);
    // 1: single-kernel lookback scan (writes rowptr/pos, zeroes cnt)
    k_scan<<<SCAN_BLOCKS, 256>>>();
    // 2: scatter into CSR, 8 edges/thread, dst premultiplied
    k_scatter<<<scatGrid, TPB>>>(ii_src, ii_dst, ii_val, Eii);

    // 3-5: pull-based LightGCN layers (idx 3 = profiled launch)
    k_spmm_pull<<<rowGrid, TPB>>>(h0, h1, att, 0);  // half(emb) -> e1
    k_spmm_pull<<<rowGrid, TPB>>>(h1, h2, att, 1);  // e1 -> e2
    k_spmm_pull<<<rowGrid, TPB>>>(h2, h0, att, 2);  // e2 -> e3 (reuse h0)

    // 6: fold layers into fp32 sum (= 4 * all_items)
    k_post<<<nb8Grid, TPB>>>(emb);

    // 7: flag batch users + zero their rows
    k_flag_zero<<<(Bp * 16 + TPB - 1) / TPB, TPB>>>(users, Bp);
    // 8: compact batch-user edges;  9: process compacted list
    k_ui_filter<<<(Eui + TPB - 1) / TPB, TPB>>>(ui_src, ui_dst, ui_val, Eui);
    k_ui_gather<<<1184, TPB>>>();
    // 10: final per-pair dots
    k_dot<<<(Bp * 32 + TPB - 1) / TPB, TPB>>>(users, items, (float*)d_out, Bp);
}